// round 3
// baseline (speedup 1.0000x reference)
#include <cuda_runtime.h>

// FlowNet2 Resample2d (kernel_size=1) bilinear warp — L1-wavefront-optimized.
// input1: [B, C, H, W] float, input2 (flow): [B, 2, H, W] float
//
// Structural trick: TL/TR (and BL/BR) gathers live in the same cache lines.
// One aligned LDG.128 at e = xL & ~3 yields both v[xL] and v[xL+1] for all
// lanes except xL%4==3, which take a sparse predicated fixup LDG.32.
// This replaces 4 full-warp-span gather requests per channel with 2 full-span
// LDG.128s + 2 quarter-density fixups, cutting L1 wavefronts and LSU slots.

#define BB 8
#define CC 32
#define HH 512
#define WW 512
#define HWSZ (HH * WW)   // 2^18

__device__ __forceinline__ float pick4(float4 q, int i) {
    // q[i] without local-memory indexing: 2-level select
    float a = (i & 2) ? q.z : q.x;
    float b = (i & 2) ? q.w : q.y;
    return (i & 1) ? b : a;
}

__global__ __launch_bounds__(256, 6)
void resample2d_kernel(const float* __restrict__ in1,
                       const float* __restrict__ flow,
                       float* __restrict__ out) {
    int pix = blockIdx.x * 256 + threadIdx.x;   // grid sized exactly

    int b  = pix >> 18;            // / HWSZ
    int hw = pix & (HWSZ - 1);
    int h  = hw >> 9;              // / WW
    int w  = hw & (WW - 1);

    const float* fl = flow + ((size_t)b << 19); // b * 2 * HWSZ
    float dx = __ldg(fl + hw);
    float dy = __ldg(fl + HWSZ + hw);

    float xf = (float)w + dx;
    float yf = (float)h + dy;
    float x0 = floorf(xf);
    float y0 = floorf(yf);
    float alpha = xf - x0;   // unclamped fractional weights
    float beta  = yf - y0;

    int ix0 = (int)x0;
    int iy0 = (int)y0;
    int xL = min(max(ix0,     0), WW - 1);
    int xR = min(max(ix0 + 1, 0), WW - 1);
    int yT = min(max(iy0,     0), HH - 1);
    int yB = min(max(iy0 + 1, 0), HH - 1);

    float wTR = alpha * (1.0f - beta);
    float wBL = (1.0f - alpha) * beta;
    float wBR = alpha * beta;
    float wTL = 1.0f - wTR - wBL - wBR;

    // Aligned 4-element window [e, e+3] containing xL (and xR unless iR==4).
    int e  = xL & ~3;              // 0..508, so e+3 <= 511: never OOB in-row
    int iL = xL - e;               // 0..3
    int iR = xR - e;               // 0..4  (xR == xL at right border)
    bool fix = (iR == 4);          // need v[e+4] == v[xR] via scalar load
    int iRs = fix ? 3 : iR;        // safe select index (overwritten if fix)

    int rT = yT << 9;
    int rB = yB << 9;

    const float* base = in1 + ((size_t)b << 23);   // b * C * HWSZ
    const float* pT = base + rT + e;               // 16B-aligned
    const float* pB = base + rB + e;
    float* op = out + ((size_t)b << 23) + hw;

    #pragma unroll 4
    for (int c = 0; c < CC; c++) {
        int off = c << 18;   // c * HWSZ
        float4 qT = __ldg((const float4*)(pT + off));
        float4 qB = __ldg((const float4*)(pB + off));

        float vTL = pick4(qT, iL);
        float vBL = pick4(qB, iL);
        float vTR = pick4(qT, iRs);
        float vBR = pick4(qB, iRs);
        if (fix) {
            vTR = __ldg(pT + off + 4);   // e+4 == xR here
            vBR = __ldg(pB + off + 4);
        }

        op[off] = wTL * vTL + wTR * vTR + wBL * vBL + wBR * vBR;
    }
}

extern "C" void kernel_launch(void* const* d_in, const int* in_sizes, int n_in,
                              void* d_out, int out_size) {
    const float* input1 = (const float*)d_in[0];
    const float* input2 = (const float*)d_in[1];
    float* out = (float*)d_out;

    const int total_pix = BB * HWSZ;               // 2,097,152
    const int threads = 256;
    const int blocks = total_pix / threads;        // 8192 (exact)
    resample2d_kernel<<<blocks, threads>>>(input1, input2, out);
}

// round 4
// speedup vs baseline: 1.5138x; 1.5138x over previous
#include <cuda_runtime.h>

// FlowNet2 Resample2d (kernel_size=1) bilinear warp.
// input1: [B, C, H, W] float, input2 (flow): [B, 2, H, W] float
//
// L1-wavefront-bound. Trick vs R2: fetch each row's (xL, xL+1) pair with one
// LDG.64 at the even-aligned address e2 = xL & ~1. Aligned 8B float pairs
// never cross a 32B sector, so the request touches exactly the TL sector set
// (~3.5 wavefronts) and its return floor is only 2 wavefronts — unlike the
// failed LDG.128 variant (4-wavefront floor). Odd-xL lanes take a
// half-density LDG.32 fixup for xR. Net: ~7.0 -> ~5.5 wavefronts per row.

#define BB 8
#define CC 32
#define HH 512
#define WW 512
#define HWSZ (HH * WW)   // 2^18

__global__ __launch_bounds__(256, 6)
void resample2d_kernel(const float* __restrict__ in1,
                       const float* __restrict__ flow,
                       float* __restrict__ out) {
    int pix = blockIdx.x * 256 + threadIdx.x;   // grid sized exactly

    int b  = pix >> 18;            // / HWSZ
    int hw = pix & (HWSZ - 1);
    int h  = hw >> 9;              // / WW
    int w  = hw & (WW - 1);

    const float* fl = flow + ((size_t)b << 19); // b * 2 * HWSZ
    float dx = __ldg(fl + hw);
    float dy = __ldg(fl + HWSZ + hw);

    float xf = (float)w + dx;
    float yf = (float)h + dy;
    float x0 = floorf(xf);
    float y0 = floorf(yf);
    float alpha = xf - x0;   // unclamped fractional weights
    float beta  = yf - y0;

    int ix0 = (int)x0;
    int iy0 = (int)y0;
    int xL = min(max(ix0,     0), WW - 1);
    int xR = min(max(ix0 + 1, 0), WW - 1);   // xR in {xL, xL+1}
    int yT = min(max(iy0,     0), HH - 1);
    int yB = min(max(iy0 + 1, 0), HH - 1);

    float wTR = alpha * (1.0f - beta);
    float wBL = (1.0f - alpha) * beta;
    float wBR = alpha * beta;
    float wTL = 1.0f - wTR - wBL - wBR;

    int e2 = xL & ~1;              // even-aligned pair base, 0..510 (in-row safe)
    int iL = xL - e2;              // 0 or 1
    int iR = xR - e2;              // 0, 1, or 2
    bool selL = (iL == 1);
    bool selR = (iR == 1);
    bool fix  = (iR == 2);         // xR is outside the aligned pair

    int rT = yT << 9;
    int rB = yB << 9;

    const float* base = in1 + ((size_t)b << 23);   // b * C * HWSZ
    const float* pT2  = base + rT + e2;            // 8B-aligned
    const float* pB2  = base + rB + e2;
    const float* pTf  = base + rT + xR;            // fixup addresses
    const float* pBf  = base + rB + xR;
    float* op = out + ((size_t)b << 23) + hw;

    #pragma unroll 4
    for (int c = 0; c < CC; c++) {
        int off = c << 18;   // c * HWSZ
        float2 qT = __ldg((const float2*)(pT2 + off));
        float2 qB = __ldg((const float2*)(pB2 + off));

        float vTL = selL ? qT.y : qT.x;
        float vBL = selL ? qB.y : qB.x;
        float vTR = selR ? qT.y : qT.x;
        float vBR = selR ? qB.y : qB.x;
        if (fix) {
            vTR = __ldg(pTf + off);
            vBR = __ldg(pBf + off);
        }

        op[off] = wTL * vTL + wTR * vTR + wBL * vBL + wBR * vBR;
    }
}

extern "C" void kernel_launch(void* const* d_in, const int* in_sizes, int n_in,
                              void* d_out, int out_size) {
    const float* input1 = (const float*)d_in[0];
    const float* input2 = (const float*)d_in[1];
    float* out = (float*)d_out;

    const int total_pix = BB * HWSZ;               // 2,097,152
    const int threads = 256;
    const int blocks = total_pix / threads;        // 8192 (exact)
    resample2d_kernel<<<blocks, threads>>>(input1, input2, out);
}